// round 8
// baseline (speedup 1.0000x reference)
#include <cuda_runtime.h>
#include <cuda_bf16.h>
#include <cstdint>

#define BATCH 4
#define HW    65536           // 256*256 pixels per (batch,channel)
#define N2    (HW / 2)        // 32768 float2s per channel
#define KBINS 512             // 8^3 bins
#define GX    37              // 37*4 = 148 CTAs = exactly 1 per SM
#define NTHR  1024            // 32 warps/SM (proven equivalent to 64)
// -1 / (49 * 2*sigma^2), sigma = 0.02
#define NEG_COEF (-25.510204081632653f)
// tail truncation: far-bin relative weight at f=0.37 is exp(-25.51*0.26)=1.3e-3
#define TLO 0.37f
#define THI 0.63f

// Scratch (no cudaMalloc). Zero at module load; last block per batch resets
// it each run, preserving the invariant across graph replays.
__device__ float        g_hist[BATCH * KBINS];
__device__ unsigned int g_count[BATCH];

// Predicated shared-memory reduction: single @p RED.SHARED instruction,
// no BSSY/BSYNC branch pair.
__device__ __forceinline__ void red_sh_pred(uint32_t addr, float val, bool pred) {
    asm volatile(
        "{\n\t"
        ".reg .pred p;\n\t"
        "setp.ne.u32 p, %2, 0;\n\t"
        "@p red.shared.add.f32 [%0], %1;\n\t"
        "}"
        :: "r"(addr), "f"(val), "r"((unsigned)pred) : "memory");
}

__global__ __launch_bounds__(NTHR, 1)
void dh_fused_kernel(const float* __restrict__ x, float* __restrict__ out) {
    __shared__ float sh[KBINS];     // block-private histogram
    __shared__ float red[32];
    __shared__ int   s_last;

    const int b   = blockIdx.y;
    const int tid = threadIdx.x;

    if (tid < KBINS) sh[tid] = 0.0f;
    __syncthreads();

    // balanced contiguous float2 range per block: 885 or 886 (<= 1024)
    const float* __restrict__ xb = x + (size_t)b * 3 * HW;
    const int start = (int)(((unsigned)blockIdx.x       * N2) / GX);
    const int end   = (int)(((unsigned)(blockIdx.x + 1) * N2) / GX);
    const int i2    = start + tid;

    if (i2 < end) {
        const float2 vx2 = __ldg((const float2*)(xb)          + i2);
        const float2 vy2 = __ldg((const float2*)(xb +     HW) + i2);
        const float2 vz2 = __ldg((const float2*)(xb + 2 * HW) + i2);
        const float* vxp = (const float*)&vx2;
        const float* vyp = (const float*)&vy2;
        const float* vzp = (const float*)&vz2;

        #pragma unroll
        for (int j = 0; j < 2; ++j) {
            const float tx = vxp[j] * 7.0f;
            const float ty = vyp[j] * 7.0f;
            const float tz = vzp[j] * 7.0f;
            const int ix = min((int)tx, 6);
            const int iy = min((int)ty, 6);
            const int iz = min((int)tz, 6);
            const float fx = tx - (float)ix;
            const float fy = ty - (float)iy;
            const float fz = tz - (float)iz;
            const float gx = 1.0f - fx, gy = 1.0f - fy, gz = 1.0f - fz;

            const float wx0 = __expf(NEG_COEF * fx * fx);
            const float wx1 = __expf(NEG_COEF * gx * gx);
            const float wy0 = __expf(NEG_COEF * fy * fy);
            const float wy1 = __expf(NEG_COEF * gy * gy);
            float       wz0 = __expf(NEG_COEF * fz * fz);
            float       wz1 = __expf(NEG_COEF * gz * gz);

            // exact per-pixel normalizer (all 6 weights; +1e-8 matters)
            const float S   = (wx0 + wx1) * (wy0 + wy1) * (wz0 + wz1);
            const float inv = __fdividef(1.0f, S + 1e-8f);
            wz0 *= inv;
            wz1 *= inv;

            const bool px0 = fx < THI, px1 = fx > TLO;
            const bool py0 = fy < THI, py1 = fy > TLO;
            const bool pz0 = fz < THI, pz1 = fz > TLO;

            const float wyz00 = wy0 * wz0, wyz01 = wy0 * wz1;
            const float wyz10 = wy1 * wz0, wyz11 = wy1 * wz1;

            const uint32_t base =
                (uint32_t)__cvta_generic_to_shared(&sh[ix * 64 + iy * 8 + iz]);

            red_sh_pred(base +  0*4, wx0 * wyz00, px0 && py0 && pz0);
            red_sh_pred(base +  1*4, wx0 * wyz01, px0 && py0 && pz1);
            red_sh_pred(base +  8*4, wx0 * wyz10, px0 && py1 && pz0);
            red_sh_pred(base +  9*4, wx0 * wyz11, px0 && py1 && pz1);
            red_sh_pred(base + 64*4, wx1 * wyz00, px1 && py0 && pz0);
            red_sh_pred(base + 65*4, wx1 * wyz01, px1 && py0 && pz1);
            red_sh_pred(base + 72*4, wx1 * wyz10, px1 && py1 && pz0);
            red_sh_pred(base + 73*4, wx1 * wyz11, px1 && py1 && pz1);
        }
    }

    __syncthreads();

    // flush block-private histogram: one bin per thread (tid < 512);
    // ~37 global adds per address -> no L2 serialization problem
    if (tid < KBINS) {
        atomicAdd(&g_hist[b * KBINS + tid], sh[tid]);
    }

    // single release fence per CTA: bar.sync gives happens-before from all
    // threads' REDs to tid0's fence; the ticket atomic publishes them.
    __syncthreads();
    if (tid == 0) {
        __threadfence();
        const unsigned t = atomicAdd(&g_count[b], 1u);
        s_last = (t == gridDim.x - 1) ? 1 : 0;
    }
    __syncthreads();

    if (s_last) {
        if (tid == 0) __threadfence();   // acquire side
        __syncthreads();
        const float v = (tid < KBINS) ? __ldcg(&g_hist[b * KBINS + tid]) : 0.0f;

        float s = v;
        #pragma unroll
        for (int o = 16; o > 0; o >>= 1) s += __shfl_xor_sync(0xffffffffu, s, o);
        if ((tid & 31) == 0) red[tid >> 5] = s;
        __syncthreads();

        float total = 0.0f;
        #pragma unroll
        for (int k = 0; k < 32; ++k) total += red[k];

        if (tid < KBINS) {
            out[b * KBINS + tid] = v * __fdividef(1.0f, total + 1e-8f);
            // restore zero-invariant for the next graph replay
            g_hist[b * KBINS + tid] = 0.0f;
        }
        if (tid == 0) g_count[b] = 0u;
    }
}

extern "C" void kernel_launch(void* const* d_in, const int* in_sizes, int n_in,
                              void* d_out, int out_size) {
    const float* x = (const float*)d_in[0];
    float* out = (float*)d_out;

    dim3 grid(GX, BATCH);
    dh_fused_kernel<<<grid, NTHR>>>(x, out);
}

// round 9
// speedup vs baseline: 1.0030x; 1.0030x over previous
#include <cuda_runtime.h>
#include <cuda_bf16.h>
#include <cstdint>

#define BATCH 4
#define HW    65536           // 256*256 pixels per (batch,channel)
#define N2    (HW / 2)        // 32768 float2s per channel
#define KBINS 512             // 8^3 bins
#define GX    37              // 37*4 = 148 CTAs = exactly 1 per SM
#define NTHR  1024
// C = 1/(49 * 2*sigma^2), sigma=0.02; sigmoid arg coefficient
#define CC (25.510204081632653f)
// tail truncation: far-axis fraction u at f=0.37 is sigmoid(-25.51*0.26)=1.3e-3
#define TLO 0.37f
#define THI 0.63f

// Scratch (no cudaMalloc). Zero at module load; last block per batch resets
// it each run, preserving the invariant across graph replays.
__device__ float        g_hist[BATCH * KBINS];
__device__ unsigned int g_count[BATCH];

// Predicated shared-memory reduction: single @p RED.SHARED instruction,
// no BSSY/BSYNC branch pair.
__device__ __forceinline__ void red_sh_pred(uint32_t addr, float val, bool pred) {
    asm volatile(
        "{\n\t"
        ".reg .pred p;\n\t"
        "setp.ne.u32 p, %2, 0;\n\t"
        "@p red.shared.add.f32 [%0], %1;\n\t"
        "}"
        :: "r"(addr), "f"(val), "r"((unsigned)pred) : "memory");
}

__global__ __launch_bounds__(NTHR, 1)
void dh_fused_kernel(const float* __restrict__ x, float* __restrict__ out) {
    __shared__ float sh[KBINS];     // block-private histogram
    __shared__ float red[32];
    __shared__ int   s_last;

    const int b   = blockIdx.y;
    const int tid = threadIdx.x;

    if (tid < KBINS) sh[tid] = 0.0f;
    __syncthreads();

    // balanced contiguous float2 range per block: 885 or 886 (<= 1024)
    const float* __restrict__ xb = x + (size_t)b * 3 * HW;
    const int start = (int)(((unsigned)blockIdx.x       * N2) / GX);
    const int end   = (int)(((unsigned)(blockIdx.x + 1) * N2) / GX);
    const int i2    = start + tid;

    if (i2 < end) {
        const float2 vx2 = __ldg((const float2*)(xb)          + i2);
        const float2 vy2 = __ldg((const float2*)(xb +     HW) + i2);
        const float2 vz2 = __ldg((const float2*)(xb + 2 * HW) + i2);
        const float* vxp = (const float*)&vx2;
        const float* vyp = (const float*)&vy2;
        const float* vzp = (const float*)&vz2;

        #pragma unroll
        for (int j = 0; j < 2; ++j) {
            const float tx = vxp[j] * 7.0f;
            const float ty = vyp[j] * 7.0f;
            const float tz = vzp[j] * 7.0f;
            const int ix = min((int)tx, 6);
            const int iy = min((int)ty, 6);
            const int iz = min((int)tz, 6);
            const float fx = tx - (float)ix;
            const float fy = ty - (float)iy;
            const float fz = tz - (float)iz;

            // per-axis normalized weight is a sigmoid:
            //   u0 = wx0/(wx0+wx1) = 1/(1+exp(C*(2f-1))),  u1 = e*u0
            // (drops the +1e-8 normalizer term: affects only pixels with
            //  f~0.5 on ALL axes, ~6e-5 of pixels, per-bin error ~2e-5)
            const float ex = __expf(__fmaf_rn(fx, 2.0f * CC, -CC));
            const float ey = __expf(__fmaf_rn(fy, 2.0f * CC, -CC));
            const float ez = __expf(__fmaf_rn(fz, 2.0f * CC, -CC));
            const float ux0 = __fdividef(1.0f, 1.0f + ex);
            const float uy0 = __fdividef(1.0f, 1.0f + ey);
            const float uz0 = __fdividef(1.0f, 1.0f + ez);
            const float ux1 = ex * ux0;
            const float uy1 = ey * uy0;
            const float uz1 = ez * uz0;

            const bool px0 = fx < THI, px1 = fx > TLO;
            const bool py0 = fy < THI, py1 = fy > TLO;
            const bool pz0 = fz < THI, pz1 = fz > TLO;

            const float uyz00 = uy0 * uz0, uyz01 = uy0 * uz1;
            const float uyz10 = uy1 * uz0, uyz11 = uy1 * uz1;

            const uint32_t base =
                (uint32_t)__cvta_generic_to_shared(&sh[ix * 64 + iy * 8 + iz]);

            red_sh_pred(base +  0*4, ux0 * uyz00, px0 && py0 && pz0);
            red_sh_pred(base +  1*4, ux0 * uyz01, px0 && py0 && pz1);
            red_sh_pred(base +  8*4, ux0 * uyz10, px0 && py1 && pz0);
            red_sh_pred(base +  9*4, ux0 * uyz11, px0 && py1 && pz1);
            red_sh_pred(base + 64*4, ux1 * uyz00, px1 && py0 && pz0);
            red_sh_pred(base + 65*4, ux1 * uyz01, px1 && py0 && pz1);
            red_sh_pred(base + 72*4, ux1 * uyz10, px1 && py1 && pz0);
            red_sh_pred(base + 73*4, ux1 * uyz11, px1 && py1 && pz1);
        }
    }

    __syncthreads();

    // flush block-private histogram: one bin per thread (tid < 512);
    // ~37 global adds per address -> no L2 serialization problem
    if (tid < KBINS) {
        atomicAdd(&g_hist[b * KBINS + tid], sh[tid]);
    }

    // single release fence per CTA: bar.sync gives happens-before from all
    // threads' REDs to tid0's fence; the ticket atomic publishes them.
    __syncthreads();
    if (tid == 0) {
        __threadfence();
        const unsigned t = atomicAdd(&g_count[b], 1u);
        s_last = (t == gridDim.x - 1) ? 1 : 0;
    }
    __syncthreads();

    if (s_last) {
        if (tid == 0) __threadfence();   // acquire side
        __syncthreads();
        const float v = (tid < KBINS) ? __ldcg(&g_hist[b * KBINS + tid]) : 0.0f;

        float s = v;
        #pragma unroll
        for (int o = 16; o > 0; o >>= 1) s += __shfl_xor_sync(0xffffffffu, s, o);
        if ((tid & 31) == 0) red[tid >> 5] = s;
        __syncthreads();

        float total = 0.0f;
        #pragma unroll
        for (int k = 0; k < 32; ++k) total += red[k];

        if (tid < KBINS) {
            out[b * KBINS + tid] = v * __fdividef(1.0f, total + 1e-8f);
            // restore zero-invariant for the next graph replay
            g_hist[b * KBINS + tid] = 0.0f;
        }
        if (tid == 0) g_count[b] = 0u;
    }
}

extern "C" void kernel_launch(void* const* d_in, const int* in_sizes, int n_in,
                              void* d_out, int out_size) {
    const float* x = (const float*)d_in[0];
    float* out = (float*)d_out;

    dim3 grid(GX, BATCH);
    dh_fused_kernel<<<grid, NTHR>>>(x, out);
}